// round 13
// baseline (speedup 1.0000x reference)
#include <cuda_runtime.h>

// Batched 256-point complex DFT, out = FFT(x) / sqrt(256).
// Four-step: 256 = 16 x 16. 16 threads/frame, 4 frames per 64-thread block,
// FOUR frame-groups per block with rolling register double-buffering:
//   load A<-g0, B<-g1 | proc A (B in flight) | load A<-g2 | proc B (A in
//   flight) | load B<-g3 | proc A (B in flight) | proc B
// -> 3 of 4 process phases have a full 64-load batch outstanding (vs 1 of 2
// in the 2-group version) at IDENTICAL peak register liveness (~108 regs).
// NO register caps (regressed in R4/R10). Per-array load batching and
// per-plane store splitting retained (DRAM row locality).
// W16 twiddles immediates; W256^{t*k}/16 via register power tree, amortized
// over 4 groups. Transpose via padded float2 shared, __syncwarp only.

#define NPT      256
#define FPB      4
#define GRPS     4
#define BLOCK    64
#define ROWS     17                 // padded row stride, float2 units
#define FS2      (16 * ROWS)        // frame stride, float2 units (272)

__device__ __forceinline__ float2 cmul(float2 a, float2 b)
{
    return make_float2(a.x * b.x - a.y * b.y,
                       a.x * b.y + a.y * b.x);
}

__device__ __forceinline__ void dft4(
    float& r0, float& i0, float& r1, float& i1,
    float& r2, float& i2, float& r3, float& i3)
{
    float t0r = r0 + r2, t0i = i0 + i2;
    float t1r = r0 - r2, t1i = i0 - i2;
    float t2r = r1 + r3, t2i = i1 + i3;
    float t3r = r1 - r3, t3i = i1 - i3;
    r0 = t0r + t2r;  i0 = t0i + t2i;
    r2 = t0r - t2r;  i2 = t0i - t2i;
    r1 = t1r + t3i;  i1 = t1i - t3r;   // t1 - i*t3
    r3 = t1r - t3i;  i3 = t1i + t3r;   // t1 + i*t3
}

// In-register forward 16-pt DFT (two radix-4 stages, DIT).
// Output X[4*k1+k2] lives in slot (4*k2+k1); callers remap with rev4().
__device__ __forceinline__ void fft16(float* xr, float* xi)
{
    constexpr float WR[10] = {
        1.f,  0.92387953251128674f,  0.70710678118654752f,  0.38268343236508977f,
        0.f, -0.38268343236508977f, -0.70710678118654752f, -0.92387953251128674f,
       -1.f, -0.92387953251128674f };
    constexpr float WI[10] = {
        0.f, -0.38268343236508977f, -0.70710678118654752f, -0.92387953251128674f,
       -1.f, -0.92387953251128674f, -0.70710678118654752f, -0.38268343236508977f,
        0.f,  0.38268343236508977f };

#pragma unroll
    for (int n1 = 0; n1 < 4; n1++) {
        dft4(xr[n1],    xi[n1],
             xr[n1+4],  xi[n1+4],
             xr[n1+8],  xi[n1+8],
             xr[n1+12], xi[n1+12]);
    }
#pragma unroll
    for (int n1 = 1; n1 < 4; n1++) {
#pragma unroll
        for (int k2 = 1; k2 < 4; k2++) {
            int s = n1 + 4 * k2;
            int m = n1 * k2;               // 1..9
            float wr = WR[m], wi = WI[m];
            float ar = xr[s], ai = xi[s];
            xr[s] = ar * wr - ai * wi;
            xi[s] = ar * wi + ai * wr;
        }
    }
#pragma unroll
    for (int k2 = 0; k2 < 4; k2++) {
        dft4(xr[4*k2+0], xi[4*k2+0],
             xr[4*k2+1], xi[4*k2+1],
             xr[4*k2+2], xi[4*k2+2],
             xr[4*k2+3], xi[4*k2+3]);
    }
}

__device__ __forceinline__ int rev4(int k) { return ((k & 3) << 2) | (k >> 2); }

// Per-array grouped strided loads for one frame (DRAM row locality).
__device__ __forceinline__ void load_group(
    const float* __restrict__ xr, const float* __restrict__ xi,
    size_t frame, int t, float* r, float* i)
{
    const float* xrp = xr + frame * NPT;
    const float* xip = xi + frame * NPT;
#pragma unroll
    for (int n2 = 0; n2 < 16; n2++) r[n2] = __ldcs(xrp + n2 * 16 + t);
#pragma unroll
    for (int n2 = 0; n2 < 16; n2++) i[n2] = __ldcs(xip + n2 * 16 + t);
}

// FFT + twiddle + transpose + second FFT + stores for one frame.
__device__ __forceinline__ void process_frame(
    float* ar, float* ai, float2* s, int t,
    const float2* Q, const float2* L,
    float* __restrict__ orp, float* __restrict__ oip)
{
    fft16(ar, ai);

#pragma unroll
    for (int k = 0; k < 16; k++) {
        int sl = rev4(k);
        float2 wk = cmul(Q[k >> 2], L[k & 3]);
        float2 v  = make_float2(ar[sl], ai[sl]);
        s[k * ROWS + t] = cmul(v, wk);
    }
    __syncwarp();                        // transpose is intra-warp

    float br[16], bi[16];
#pragma unroll
    for (int n1 = 0; n1 < 16; n1++) {
        float2 v = s[t * ROWS + n1];
        br[n1] = v.x;  bi[n1] = v.y;
    }
    __syncwarp();                        // WAR guard: buffer reused next group
    fft16(br, bi);

    // stores split per plane: each 16-store run stays in one 1KB region
#pragma unroll
    for (int k1 = 0; k1 < 16; k1++) {
        __stcs(orp + k1 * 16 + t, br[rev4(k1)]);
    }
#pragma unroll
    for (int k1 = 0; k1 < 16; k1++) {
        __stcs(oip + k1 * 16 + t, bi[rev4(k1)]);
    }
}

__global__ void __launch_bounds__(BLOCK)
dft256_kernel(const float* __restrict__ xr, const float* __restrict__ xi,
              const float* __restrict__ Wr, const float* __restrict__ Wi,
              float* __restrict__ outR, float* __restrict__ outI)
{
    __shared__ float2 sh[FPB * FS2];     // transpose buffer (reused per group)

    const int tid = threadIdx.x;
    const int f = tid >> 4;              // frame within group
    const int t = tid & 15;              // lane within frame (half-warp local)

    const size_t fr0 = ((size_t)blockIdx.x * GRPS) * FPB + f;
    const size_t fr1 = fr0 + FPB;
    const size_t fr2 = fr0 + 2 * FPB;
    const size_t fr3 = fr0 + 3 * FPB;

    // ---- prologue: fill both buffers (128 outstanding loads/thread-pair) ----
    float Arr[16], Ari[16], Brr[16], Bri[16];
    load_group(xr, xi, fr0, t, Arr, Ari);
    load_group(xr, xi, fr1, t, Brr, Bri);

    // ---- step-2 twiddles in registers (amortized over 4 groups) ----
    float2 w1 = make_float2(Wr[NPT + t], Wi[NPT + t]);   // W256^t
    float2 w2 = cmul(w1, w1);
    float2 w3 = cmul(w2, w1);
    float2 w4 = cmul(w2, w2);
    float2 w8 = cmul(w4, w4);
    float2 L[4] = { make_float2(1.f, 0.f), w1, w2, w3 };
    float2 Q[4];
    Q[0] = make_float2(0.0625f, 0.f);
    Q[1] = make_float2(0.0625f * w4.x, 0.0625f * w4.y);
    Q[2] = make_float2(0.0625f * w8.x, 0.0625f * w8.y);
    Q[3] = cmul(Q[2], w4);               // w12 / 16

    float2* s = sh + f * FS2;

    // ---- rolling pipeline: 3 of 4 process phases overlap a load batch ----
    process_frame(Arr, Ari, s, t, Q, L,
                  outR + fr0 * NPT, outI + fr0 * NPT);   // B(g1) in flight
    load_group(xr, xi, fr2, t, Arr, Ari);                // refill A

    process_frame(Brr, Bri, s, t, Q, L,
                  outR + fr1 * NPT, outI + fr1 * NPT);   // A(g2) in flight
    load_group(xr, xi, fr3, t, Brr, Bri);                // refill B

    process_frame(Arr, Ari, s, t, Q, L,
                  outR + fr2 * NPT, outI + fr2 * NPT);   // B(g3) in flight

    process_frame(Brr, Bri, s, t, Q, L,
                  outR + fr3 * NPT, outI + fr3 * NPT);   // tail
}

extern "C" void kernel_launch(void* const* d_in, const int* in_sizes, int n_in,
                              void* d_out, int out_size)
{
    const float* x_real = (const float*)d_in[0];
    const float* x_imag = (const float*)d_in[1];
    const float* W_real = (const float*)d_in[2];
    const float* W_imag = (const float*)d_in[3];

    const size_t nframes = (size_t)in_sizes[0] / NPT;   // 262144
    float* outR = (float*)d_out;
    float* outI = outR + nframes * NPT;                 // [real | imag]

    const int grid = (int)(nframes / (FPB * GRPS));     // 16384
    dft256_kernel<<<grid, BLOCK>>>(x_real, x_imag, W_real, W_imag, outR, outI);
}

// round 14
// speedup vs baseline: 1.0226x; 1.0226x over previous
#include <cuda_runtime.h>

// FINAL (reverted to R12, session best: 155.65us, DRAM 84.7-85.0%, 6.7+ TB/s).
//
// Batched 256-point complex DFT, out = FFT(x) / sqrt(256).
// Four-step: 256 = 16 x 16. 16 threads/frame, 4 frames per 64-thread block,
// TWO frame-groups per block, register double-buffered (deep per-warp MLP:
// ~112 front-batched outstanding loads while the previous group computes).
// Session findings baked in:
//  - FFT beats tcgen05 matmul here: traffic-bound problem, 1.07GB mandatory
//    HBM traffic => ~150us floor; all structures pin at 83-85% of HBM spec.
//  - NEVER cap registers (R4/R10): MLP from front-batched loads is worth
//    more than occupancy on this chip.
//  - cp.async staging (R9), smem-staged vector I/O (R2), 4-group rolling
//    pipelines (R13) all regress vs register double-buffering.
//  - Per-array load batching + per-plane store splitting help DRAM row
//    locality (R11). Streaming hints (.cs) on all global traffic.
// W16 twiddles are immediates; W256^{t*k}/16 via register power tree from
// row 1 of the input W matrix (exact twiddles => rel_err ~3.5e-7).
// Transpose via padded float2 shared, __syncwarp only (no block barriers).

#define NPT      256
#define FPB      4
#define BLOCK    64
#define ROWS     17                 // padded row stride, float2 units
#define FS2      (16 * ROWS)        // frame stride, float2 units (272)

__device__ __forceinline__ float2 cmul(float2 a, float2 b)
{
    return make_float2(a.x * b.x - a.y * b.y,
                       a.x * b.y + a.y * b.x);
}

__device__ __forceinline__ void dft4(
    float& r0, float& i0, float& r1, float& i1,
    float& r2, float& i2, float& r3, float& i3)
{
    float t0r = r0 + r2, t0i = i0 + i2;
    float t1r = r0 - r2, t1i = i0 - i2;
    float t2r = r1 + r3, t2i = i1 + i3;
    float t3r = r1 - r3, t3i = i1 - i3;
    r0 = t0r + t2r;  i0 = t0i + t2i;
    r2 = t0r - t2r;  i2 = t0i - t2i;
    r1 = t1r + t3i;  i1 = t1i - t3r;   // t1 - i*t3
    r3 = t1r - t3i;  i3 = t1i + t3r;   // t1 + i*t3
}

// In-register forward 16-pt DFT (two radix-4 stages, DIT).
// Output X[4*k1+k2] lives in slot (4*k2+k1); callers remap with rev4().
__device__ __forceinline__ void fft16(float* xr, float* xi)
{
    constexpr float WR[10] = {
        1.f,  0.92387953251128674f,  0.70710678118654752f,  0.38268343236508977f,
        0.f, -0.38268343236508977f, -0.70710678118654752f, -0.92387953251128674f,
       -1.f, -0.92387953251128674f };
    constexpr float WI[10] = {
        0.f, -0.38268343236508977f, -0.70710678118654752f, -0.92387953251128674f,
       -1.f, -0.92387953251128674f, -0.70710678118654752f, -0.38268343236508977f,
        0.f,  0.38268343236508977f };

#pragma unroll
    for (int n1 = 0; n1 < 4; n1++) {
        dft4(xr[n1],    xi[n1],
             xr[n1+4],  xi[n1+4],
             xr[n1+8],  xi[n1+8],
             xr[n1+12], xi[n1+12]);
    }
#pragma unroll
    for (int n1 = 1; n1 < 4; n1++) {
#pragma unroll
        for (int k2 = 1; k2 < 4; k2++) {
            int s = n1 + 4 * k2;
            int m = n1 * k2;               // 1..9
            float wr = WR[m], wi = WI[m];
            float ar = xr[s], ai = xi[s];
            xr[s] = ar * wr - ai * wi;
            xi[s] = ar * wi + ai * wr;
        }
    }
#pragma unroll
    for (int k2 = 0; k2 < 4; k2++) {
        dft4(xr[4*k2+0], xi[4*k2+0],
             xr[4*k2+1], xi[4*k2+1],
             xr[4*k2+2], xi[4*k2+2],
             xr[4*k2+3], xi[4*k2+3]);
    }
}

__device__ __forceinline__ int rev4(int k) { return ((k & 3) << 2) | (k >> 2); }

// FFT + twiddle + transpose + second FFT + stores for one frame.
__device__ __forceinline__ void process_frame(
    float* ar, float* ai, float2* s, int t,
    const float2* Q, const float2* L,
    float* __restrict__ orp, float* __restrict__ oip)
{
    fft16(ar, ai);

#pragma unroll
    for (int k = 0; k < 16; k++) {
        int sl = rev4(k);
        float2 wk = cmul(Q[k >> 2], L[k & 3]);
        float2 v  = make_float2(ar[sl], ai[sl]);
        s[k * ROWS + t] = cmul(v, wk);
    }
    __syncwarp();                        // transpose is intra-warp

    float br[16], bi[16];
#pragma unroll
    for (int n1 = 0; n1 < 16; n1++) {
        float2 v = s[t * ROWS + n1];
        br[n1] = v.x;  bi[n1] = v.y;
    }
    __syncwarp();                        // WAR guard: buffer reused next group
    fft16(br, bi);

    // stores split per plane: each 16-store run stays in one 1KB region
#pragma unroll
    for (int k1 = 0; k1 < 16; k1++) {
        __stcs(orp + k1 * 16 + t, br[rev4(k1)]);
    }
#pragma unroll
    for (int k1 = 0; k1 < 16; k1++) {
        __stcs(oip + k1 * 16 + t, bi[rev4(k1)]);
    }
}

__global__ void __launch_bounds__(BLOCK)
dft256_kernel(const float* __restrict__ xr, const float* __restrict__ xi,
              const float* __restrict__ Wr, const float* __restrict__ Wi,
              float* __restrict__ outR, float* __restrict__ outI)
{
    __shared__ float2 sh[FPB * FS2];     // transpose buffer (reused per group)

    const int tid = threadIdx.x;
    const int f = tid >> 4;              // frame within group
    const int t = tid & 15;              // lane within frame (half-warp local)

    const size_t frame0 = ((size_t)blockIdx.x * 2) * FPB + f;   // group 0
    const size_t frame1 = frame0 + FPB;                         // group 1
    const float* xr0 = xr + frame0 * NPT;
    const float* xi0 = xi + frame0 * NPT;
    const float* xr1 = xr + frame1 * NPT;
    const float* xi1 = xi + frame1 * NPT;

    // ---- front batch: group 0 (both planes) + group 1 real plane ----
    float ar[16], ai[16], cr[16], ci[16];
#pragma unroll
    for (int n2 = 0; n2 < 16; n2++) ar[n2] = __ldcs(xr0 + n2 * 16 + t);
#pragma unroll
    for (int n2 = 0; n2 < 16; n2++) ai[n2] = __ldcs(xi0 + n2 * 16 + t);
#pragma unroll
    for (int n2 = 0; n2 < 16; n2++) cr[n2] = __ldcs(xr1 + n2 * 16 + t);

    // ---- step-2 twiddles in registers (shared by both groups) ----
    float2 w1 = make_float2(Wr[NPT + t], Wi[NPT + t]);   // W256^t
    float2 w2 = cmul(w1, w1);
    float2 w3 = cmul(w2, w1);
    float2 w4 = cmul(w2, w2);
    float2 w8 = cmul(w4, w4);
    float2 L[4] = { make_float2(1.f, 0.f), w1, w2, w3 };
    float2 Q[4];
    Q[0] = make_float2(0.0625f, 0.f);
    Q[1] = make_float2(0.0625f * w4.x, 0.0625f * w4.y);
    Q[2] = make_float2(0.0625f * w8.x, 0.0625f * w8.y);
    Q[3] = cmul(Q[2], w4);               // w12 / 16

    float2* s = sh + f * FS2;

    // ---- group 0 step 1 ----
    fft16(ar, ai);

    // ---- group 1 imag plane issued here, overlapping group 0's
    //      transpose + second FFT + stores ----
#pragma unroll
    for (int n2 = 0; n2 < 16; n2++) ci[n2] = __ldcs(xi1 + n2 * 16 + t);

    // ---- group 0 steps 2-4 ----
#pragma unroll
    for (int k = 0; k < 16; k++) {
        int sl = rev4(k);
        float2 wk = cmul(Q[k >> 2], L[k & 3]);
        float2 v  = make_float2(ar[sl], ai[sl]);
        s[k * ROWS + t] = cmul(v, wk);
    }
    __syncwarp();

    {
        float br[16], bi[16];
#pragma unroll
        for (int n1 = 0; n1 < 16; n1++) {
            float2 v = s[t * ROWS + n1];
            br[n1] = v.x;  bi[n1] = v.y;
        }
        __syncwarp();                    // WAR guard before group 1 reuses sh
        fft16(br, bi);

        float* orp = outR + frame0 * NPT;
        float* oip = outI + frame0 * NPT;
#pragma unroll
        for (int k1 = 0; k1 < 16; k1++) {
            __stcs(orp + k1 * 16 + t, br[rev4(k1)]);
        }
#pragma unroll
        for (int k1 = 0; k1 < 16; k1++) {
            __stcs(oip + k1 * 16 + t, bi[rev4(k1)]);
        }
    }

    // ---- group 1 ----
    process_frame(cr, ci, s, t, Q, L,
                  outR + frame1 * NPT, outI + frame1 * NPT);
}

extern "C" void kernel_launch(void* const* d_in, const int* in_sizes, int n_in,
                              void* d_out, int out_size)
{
    const float* x_real = (const float*)d_in[0];
    const float* x_imag = (const float*)d_in[1];
    const float* W_real = (const float*)d_in[2];
    const float* W_imag = (const float*)d_in[3];

    const size_t nframes = (size_t)in_sizes[0] / NPT;   // 262144
    float* outR = (float*)d_out;
    float* outI = outR + nframes * NPT;                 // [real | imag]

    const int grid = (int)(nframes / (FPB * 2));        // 32768
    dft256_kernel<<<grid, BLOCK>>>(x_real, x_imag, W_real, W_imag, outR, outI);
}